// round 1
// baseline (speedup 1.0000x reference)
#include <cuda_runtime.h>
#include <cstdint>
#include <math.h>

#define N_NODES 100000
#define N_EDGES 3200000
#define D_FEAT  512
#define HID     16

// ---------------- scratch (device globals; no allocation allowed) ----------
__device__ float g_t1[N_NODES * HID];   // x @ W1
__device__ float g_h1[N_NODES * HID];   // scatter accumulator layer 1
__device__ float g_t2[N_NODES * HID];   // relu(h1+b1) @ W2
__device__ int   g_is64;

// ---------------- helpers --------------------------------------------------
__device__ __forceinline__ unsigned long long ffma2(unsigned long long a,
                                                    unsigned long long b,
                                                    unsigned long long c) {
    unsigned long long d;
    asm("fma.rn.f32x2 %0, %1, %2, %3;" : "=l"(d) : "l"(a), "l"(b), "l"(c));
    return d;
}

// ---------------- edge_index dtype detection -------------------------------
// If int64 (values in [0,100000), nonnegative), every high 32-bit word is 0.
// If int32, odd int32 slots hold real indices; P(2048 consecutive == 0) ~ 0.
__global__ void detect_kernel(const void* eiv) {
    const int* p = (const int*)eiv;
    int is64 = 1;
    for (int i = 0; i < 2048; i++) {
        if (p[2 * i + 1] != 0) { is64 = 0; break; }
    }
    g_is64 = is64;
}

// ---------------- zero accumulators ---------------------------------------
__global__ void zero_kernel(float* __restrict__ out) {
    int i = blockIdx.x * blockDim.x + threadIdx.x;
    const int total4 = N_NODES * HID / 4;   // 400000 float4s
    if (i < total4) {
        float4 z = make_float4(0.f, 0.f, 0.f, 0.f);
        ((float4*)g_h1)[i] = z;
        ((float4*)out)[i]  = z;
    }
}

// ---------------- GEMM1: t1 = x @ W1  (100000x512 @ 512x16) ---------------
// Block = 256 threads, 256 rows per block. K tiled by 8.
// FFMA2 (f32x2) packs two output columns per instruction.
#define KT 8
__global__ void gemm1_kernel(const float* __restrict__ x,
                             const float* __restrict__ W1) {
    __shared__ float Ws[D_FEAT * HID];       // 32 KB
    __shared__ float xs[256 * (KT + 1)];     // 9 KB, pad stride 9 (coprime 32)

    const int t = threadIdx.x;
    for (int i = t; i < D_FEAT * HID; i += 256) Ws[i] = W1[i];

    const int row0   = blockIdx.x * 256;
    const int my_row = row0 + t;

    unsigned long long acc[8];
#pragma unroll
    for (int j = 0; j < 8; j++) acc[j] = 0ULL;   // {0.f, 0.f}

    for (int kt = 0; kt < D_FEAT / KT; kt++) {
        const int k0 = kt * KT;
        __syncthreads();
        // stage 256 rows x KT cols, coalesced
#pragma unroll
        for (int i = 0; i < KT; i++) {
            int idx = t + 256 * i;
            int r = idx >> 3;          // KT = 8
            int kk = idx & 7;
            int gr = row0 + r;
            xs[r * (KT + 1) + kk] =
                (gr < N_NODES) ? x[(size_t)gr * D_FEAT + k0 + kk] : 0.0f;
        }
        __syncthreads();

        const float* xrow = xs + t * (KT + 1);
#pragma unroll
        for (int kk = 0; kk < KT; kk++) {
            float xv = xrow[kk];
            unsigned long long xp;
            unsigned int xb = __float_as_uint(xv);
            asm("mov.b64 %0, {%1, %1};" : "=l"(xp) : "r"(xb));
            const ulonglong2* wrow =
                (const ulonglong2*)(Ws + (k0 + kk) * HID);
#pragma unroll
            for (int j2 = 0; j2 < 4; j2++) {
                ulonglong2 wp = wrow[j2];
                acc[2 * j2]     = ffma2(xp, wp.x, acc[2 * j2]);
                acc[2 * j2 + 1] = ffma2(xp, wp.y, acc[2 * j2 + 1]);
            }
        }
    }

    if (my_row < N_NODES) {
        float o[16];
#pragma unroll
        for (int j = 0; j < 8; j++) {
            unsigned int lo, hi;
            asm("mov.b64 {%0, %1}, %2;" : "=r"(lo), "=r"(hi) : "l"(acc[j]));
            o[2 * j]     = __uint_as_float(lo);
            o[2 * j + 1] = __uint_as_float(hi);
        }
        float4* dst = (float4*)(g_t1 + (size_t)my_row * HID);
        dst[0] = make_float4(o[0], o[1], o[2], o[3]);
        dst[1] = make_float4(o[4], o[5], o[6], o[7]);
        dst[2] = make_float4(o[8], o[9], o[10], o[11]);
        dst[3] = make_float4(o[12], o[13], o[14], o[15]);
    }
}

// ---------------- edge scatter: acc[dst] += w * feat[src] ------------------
// One thread per (edge, 4-column chunk): 12.8M units, RED.128 atomics.
__global__ void scatter_kernel(const void* __restrict__ eiv,
                               const float* __restrict__ ew,
                               float* __restrict__ out, int pass) {
    long long u = (long long)blockIdx.x * blockDim.x + threadIdx.x;
    const long long total = (long long)N_EDGES * 4;
    if (u >= total) return;
    int e = (int)(u >> 2);
    int c = (int)(u & 3);

    const float* feat = (pass == 0) ? g_t1 : g_t2;
    float*       acc  = (pass == 0) ? g_h1 : out;

    long long s, d;
    if (g_is64) {
        const long long* ei = (const long long*)eiv;
        s = ei[e];
        d = ei[N_EDGES + e];
    } else {
        const int* ei = (const int*)eiv;
        s = ei[e];
        d = ei[N_EDGES + e];
    }
    float w = ew[e];
    float4 v = *(const float4*)(feat + s * HID + c * 4);
    float4 m = make_float4(w * v.x, w * v.y, w * v.z, w * v.w);
    atomicAdd((float4*)(acc + d * HID + c * 4), m);
}

// ---------------- mid: t2 = relu(h1 + b1) @ W2 -----------------------------
__global__ void mid_kernel(const float* __restrict__ b1,
                           const float* __restrict__ W2) {
    __shared__ float W2s[HID * HID];
    __shared__ float b1s[HID];
    int t = threadIdx.x;
    if (t < HID * HID) W2s[t] = W2[t];
    if (t < HID) b1s[t] = b1[t];
    __syncthreads();

    int node = blockIdx.x * blockDim.x + t;
    if (node >= N_NODES) return;

    float v[16];
    const float4* src = (const float4*)(g_h1 + (size_t)node * HID);
#pragma unroll
    for (int q = 0; q < 4; q++) {
        float4 f = src[q];
        v[4 * q] = f.x; v[4 * q + 1] = f.y; v[4 * q + 2] = f.z; v[4 * q + 3] = f.w;
    }
#pragma unroll
    for (int i = 0; i < 16; i++) v[i] = fmaxf(v[i] + b1s[i], 0.0f);

    float o[16];
#pragma unroll
    for (int j = 0; j < 16; j++) o[j] = 0.0f;
#pragma unroll
    for (int i = 0; i < 16; i++) {
        float vi = v[i];
#pragma unroll
        for (int j = 0; j < 16; j++) o[j] = fmaf(vi, W2s[i * 16 + j], o[j]);
    }

    float4* dst = (float4*)(g_t2 + (size_t)node * HID);
    dst[0] = make_float4(o[0], o[1], o[2], o[3]);
    dst[1] = make_float4(o[4], o[5], o[6], o[7]);
    dst[2] = make_float4(o[8], o[9], o[10], o[11]);
    dst[3] = make_float4(o[12], o[13], o[14], o[15]);
}

// ---------------- final: out = log_softmax(out + b2) -----------------------
__global__ void final_kernel(float* __restrict__ out,
                             const float* __restrict__ b2) {
    __shared__ float b2s[HID];
    if (threadIdx.x < HID) b2s[threadIdx.x] = b2[threadIdx.x];
    __syncthreads();

    int node = blockIdx.x * blockDim.x + threadIdx.x;
    if (node >= N_NODES) return;

    float o[16];
    float4* p = (float4*)(out + (size_t)node * HID);
#pragma unroll
    for (int q = 0; q < 4; q++) {
        float4 f = p[q];
        o[4 * q] = f.x + b2s[4 * q];
        o[4 * q + 1] = f.y + b2s[4 * q + 1];
        o[4 * q + 2] = f.z + b2s[4 * q + 2];
        o[4 * q + 3] = f.w + b2s[4 * q + 3];
    }
    float m = o[0];
#pragma unroll
    for (int j = 1; j < 16; j++) m = fmaxf(m, o[j]);
    float ssum = 0.0f;
#pragma unroll
    for (int j = 0; j < 16; j++) ssum += expf(o[j] - m);
    float lse = m + logf(ssum);
#pragma unroll
    for (int j = 0; j < 16; j++) o[j] -= lse;

    p[0] = make_float4(o[0], o[1], o[2], o[3]);
    p[1] = make_float4(o[4], o[5], o[6], o[7]);
    p[2] = make_float4(o[8], o[9], o[10], o[11]);
    p[3] = make_float4(o[12], o[13], o[14], o[15]);
}

// ---------------- launch ---------------------------------------------------
extern "C" void kernel_launch(void* const* d_in, const int* in_sizes, int n_in,
                              void* d_out, int out_size) {
    const float* x  = (const float*)d_in[0];
    const void*  ei = d_in[1];
    const float* ew = (const float*)d_in[2];
    const float* W1 = (const float*)d_in[3];
    const float* b1 = (const float*)d_in[4];
    const float* W2 = (const float*)d_in[5];
    const float* b2 = (const float*)d_in[6];
    float* out = (float*)d_out;

    detect_kernel<<<1, 1>>>(ei);
    zero_kernel<<<(N_NODES * HID / 4 + 255) / 256, 256>>>(out);
    gemm1_kernel<<<(N_NODES + 255) / 256, 256>>>(x, W1);

    const int scat_blocks = (int)(((long long)N_EDGES * 4 + 255) / 256);
    scatter_kernel<<<scat_blocks, 256>>>(ei, ew, out, 0);
    mid_kernel<<<(N_NODES + 255) / 256, 256>>>(b1, W2);
    scatter_kernel<<<scat_blocks, 256>>>(ei, ew, out, 1);
    final_kernel<<<(N_NODES + 255) / 256, 256>>>(out, b2);
}